// round 5
// baseline (speedup 1.0000x reference)
#include <cuda_runtime.h>
#include <math.h>

typedef unsigned long long ull;

#define NN 2048
#define MM 128
#define INF 256
#define HH 128
#define NP (NN/2)
#define NCHUNK 8
#define GM 4
#define PTILE 128

#define MIN_STDD 0.3023568
#define MAX_STDD 2.1920868

// ---------------- scratch ----------------
__device__ float g_S2[MM][NP][20];
__device__ float g_hdp2[3][NP][HH][2];
__device__ float g_coarse[NCHUNK][MM][9][HH];
__device__ float g_CU[MM][9][HH];

// ---------------- f32x2 helpers ----------------
__device__ __forceinline__ ull pack2(float lo, float hi){ ull r; asm("mov.b64 %0,{%1,%2};":"=l"(r):"f"(lo),"f"(hi)); return r; }
__device__ __forceinline__ float2 unpk2(ull v){ float2 f; asm("mov.b64 {%0,%1},%2;":"=f"(f.x),"=f"(f.y):"l"(v)); return f; }
__device__ __forceinline__ ull fma2(ull a, ull b, ull c){ ull d; asm("fma.rn.f32x2 %0,%1,%2,%3;":"=l"(d):"l"(a),"l"(b),"l"(c)); return d; }
__device__ __forceinline__ ull mul2(ull a, ull b){ ull d; asm("mul.rn.f32x2 %0,%1,%2;":"=l"(d):"l"(a),"l"(b)); return d; }
__device__ __forceinline__ ull add2(ull a, ull b){ ull d; asm("add.rn.f32x2 %0,%1,%2;":"=l"(d):"l"(a),"l"(b)); return d; }
__device__ __forceinline__ float ex2f(float x){ float e; asm("ex2.approx.f32 %0,%1;":"=f"(e):"f"(x)); return e; }

// ---------------- K1: spherical harmonics (n-paired layout) ----------------
__global__ void k_sh(const float* __restrict__ gc, const float* __restrict__ cc) {
    int m = blockIdx.x;
    float cx = cc[3*m], cy = cc[3*m+1], cz = cc[3*m+2];
    const float is3  = 0.5773502691896258f;
    const float is5  = 0.4472135954999579f;
    const float s3i5 = 0.7745966692414834f;
    for (int p = threadIdx.x; p < NP; p += blockDim.x) {
        float k[2][9]; float xx2[2];
        #pragma unroll
        for (int hh = 0; hh < 2; hh++) {
            int n = 2*p + hh;
            float dx = gc[3*n]   - cx;
            float dy = gc[3*n+1] - cy;
            float dz = gc[3*n+2] - cz;
            float x2 = dx*dx + dy*dy + dz*dz + 3e-20f;
            float inv = rsqrtf(x2);
            float x = dx*inv, y = dy*inv, z = dz*inv;
            xx2[hh] = x2;
            k[hh][1] = x*is3;  k[hh][2] = y*is3;  k[hh][3] = z*is3;
            k[hh][4] = s3i5*x*z; k[hh][5] = s3i5*x*y;
            k[hh][6] = (y*y - 0.5f*(x*x + z*z))*is5;
            k[hh][7] = s3i5*y*z; k[hh][8] = 0.5f*s3i5*(z*z - x*x);
        }
        float* q = &g_S2[m][p][0];
        *(float4*)(q+0)  = make_float4(k[0][1],k[1][1],k[0][2],k[1][2]);
        *(float4*)(q+4)  = make_float4(k[0][3],k[1][3],k[0][4],k[1][4]);
        *(float4*)(q+8)  = make_float4(k[0][5],k[1][5],k[0][6],k[1][6]);
        *(float4*)(q+12) = make_float4(k[0][7],k[1][7],k[0][8],k[1][8]);
        *(float4*)(q+16) = make_float4(xx2[0],xx2[1],0.f,0.f);
    }
}

// ---------------- K2: pre-MLP + down projections (128 thr, row-paired f32x2) ----------------
__global__ void __launch_bounds__(128) k_pre(const float* __restrict__ h,
                      const float* __restrict__ Wpre, const float* __restrict__ bpre,
                      const float* __restrict__ Wdown, const float* __restrict__ gw) {
    __shared__ float hT[INF][18];   // [unit][row], rows 0..15, pad to 18
    __shared__ float sT[HH][18];    // silu'ed, [unit][row]
    int n0 = blockIdx.x * 16;
    int t  = threadIdx.x;           // column w = t

    for (int idx = t; idx < 16*INF; idx += 128) {
        int r = idx >> 8, u = idx & 255;
        hT[u][r] = h[(n0 + r)*INF + u];
    }
    __syncthreads();

    ull acc[8];
    {
        float b0 = bpre[t];
        #pragma unroll
        for (int j = 0; j < 8; j++) acc[j] = pack2(b0, b0);
    }
    #pragma unroll 4
    for (int u = 0; u < INF; u++) {
        float wv = Wpre[u*HH + t];
        ull w2 = pack2(wv, wv);
        #pragma unroll
        for (int j = 0; j < 8; j++)
            acc[j] = fma2(*(const ull*)&hT[u][2*j], w2, acc[j]);
    }
    #pragma unroll
    for (int j = 0; j < 8; j++) {
        float2 a = unpk2(acc[j]);
        a.x = a.x/(1.f+__expf(-a.x)); a.y = a.y/(1.f+__expf(-a.y));
        *(ull*)&sT[t][2*j] = pack2(a.x, a.y);
    }
    __syncthreads();

    double sd = MIN_STDD + (MAX_STDD-MIN_STDD)*(double)t/127.0;
    double iv = 1.0/(2.0*sd*sd);
    const double pi15 = 5.568327996831708;
    float cw = (float)((2.0/3.0)*pow(iv,2.5)/pi15);

    ull gwc[8];
    #pragma unroll
    for (int j = 0; j < 8; j++)
        gwc[j] = pack2(gw[n0+2*j]*cw, gw[n0+2*j+1]*cw);

    int pbase = blockIdx.x * 8;
    for (int l = 0; l < 3; l++) {
        const float* Wd = Wdown + l*HH*HH;
        ull a2[8];
        #pragma unroll
        for (int j = 0; j < 8; j++) a2[j] = 0ull;
        #pragma unroll 4
        for (int u = 0; u < HH; u++) {
            float wv = Wd[u*HH + t];
            ull w2 = pack2(wv, wv);
            #pragma unroll
            for (int j = 0; j < 8; j++)
                a2[j] = fma2(*(const ull*)&sT[u][2*j], w2, a2[j]);
        }
        #pragma unroll
        for (int j = 0; j < 8; j++)
            *(ull*)&g_hdp2[l][pbase + j][t][0] = mul2(a2[j], gwc[j]);
    }
}

// ---------------- K3: main down accumulation (n-paired f32x2) ----------------
__global__ void __launch_bounds__(128) k_down() {
    __shared__ float Ssm[GM][PTILE][20];   // 40 KB
    int t  = threadIdx.x;
    int m0 = blockIdx.x * GM;
    int p0 = blockIdx.y * PTILE;

    double sd = MIN_STDD + (MAX_STDD-MIN_STDD)*(double)t/127.0;
    float niv = (float)(-1.4426950408889634/(2.0*sd*sd));
    ull niv2 = pack2(niv, niv);

    for (int i = t; i < GM*PTILE*5; i += 128) {
        int mi = i/(PTILE*5); int rem = i%(PTILE*5); int p = rem/5; int j = rem%5;
        *(float4*)&Ssm[mi][p][4*j] = *(const float4*)&g_S2[m0+mi][p0+p][4*j];
    }
    ull acc[GM][9];
    #pragma unroll
    for (int mi = 0; mi < GM; mi++)
        #pragma unroll
        for (int k = 0; k < 9; k++) acc[mi][k] = 0ull;
    __syncthreads();

    ull h0 = *(const ull*)&g_hdp2[0][p0][t][0];
    ull h1 = *(const ull*)&g_hdp2[1][p0][t][0];
    ull h2 = *(const ull*)&g_hdp2[2][p0][t][0];

    #pragma unroll 1
    for (int p = 0; p < PTILE; p++) {
        ull c0 = h0, c1 = h1, c2 = h2;
        if (p + 1 < PTILE) {
            h0 = *(const ull*)&g_hdp2[0][p0+p+1][t][0];
            h1 = *(const ull*)&g_hdp2[1][p0+p+1][t][0];
            h2 = *(const ull*)&g_hdp2[2][p0+p+1][t][0];
        }
        #pragma unroll
        for (int mi = 0; mi < GM; mi++) {
            const float* sp = &Ssm[mi][p][0];
            ulonglong2 q01 = *(const ulonglong2*)(sp);
            ulonglong2 q23 = *(const ulonglong2*)(sp + 4);
            ulonglong2 q45 = *(const ulonglong2*)(sp + 8);
            ulonglong2 q67 = *(const ulonglong2*)(sp + 12);
            ull x2p = *(const ull*)(sp + 16);
            ull qq  = mul2(x2p, niv2);
            float2 ef = unpk2(qq);
            ull ep  = pack2(ex2f(ef.x), ex2f(ef.y));
            ull rp  = mul2(ep, x2p);
            ull t0 = mul2(c0, rp), t1 = mul2(c1, rp), t2 = mul2(c2, rp);
            acc[mi][0] = add2(acc[mi][0], t0);
            acc[mi][1] = fma2(t1, q01.x, acc[mi][1]);
            acc[mi][2] = fma2(t1, q01.y, acc[mi][2]);
            acc[mi][3] = fma2(t1, q23.x, acc[mi][3]);
            acc[mi][4] = fma2(t2, q23.y, acc[mi][4]);
            acc[mi][5] = fma2(t2, q45.x, acc[mi][5]);
            acc[mi][6] = fma2(t2, q45.y, acc[mi][6]);
            acc[mi][7] = fma2(t2, q67.x, acc[mi][7]);
            acc[mi][8] = fma2(t2, q67.y, acc[mi][8]);
        }
    }
    #pragma unroll
    for (int mi = 0; mi < GM; mi++)
        #pragma unroll
        for (int k = 0; k < 9; k++) {
            float2 f = unpk2(acc[mi][k]);
            g_coarse[blockIdx.y][m0+mi][k][t] = f.x + f.y;
        }
}

// ---------------- K4: chunk reduce + CU = coarse @ Wup (one block per m) ----------------
__global__ void __launch_bounds__(128) k_cu(const float* __restrict__ Wup) {
    __shared__ float csm[9][HH];
    int m = blockIdx.x;
    int t = threadIdx.x;

    #pragma unroll
    for (int k = 0; k < 9; k++) {
        float s = 0.f;
        #pragma unroll
        for (int ch = 0; ch < NCHUNK; ch++)
            s += g_coarse[ch][m][k][t];
        csm[k][t] = s;
    }
    __syncthreads();

    const float* W0 = Wup;
    const float* W1 = Wup + HH*HH;
    const float* W2 = Wup + 2*HH*HH;
    float a[9];
    #pragma unroll
    for (int k = 0; k < 9; k++) a[k] = 0.f;
    #pragma unroll 4
    for (int u = 0; u < HH; u++) {
        float w0 = W0[u*HH + t];
        float w1 = W1[u*HH + t];
        float w2 = W2[u*HH + t];
        a[0] += csm[0][u] * w0;
        a[1] += csm[1][u] * w1;
        a[2] += csm[2][u] * w1;
        a[3] += csm[3][u] * w1;
        a[4] += csm[4][u] * w2;
        a[5] += csm[5][u] * w2;
        a[6] += csm[6][u] * w2;
        a[7] += csm[7][u] * w2;
        a[8] += csm[8][u] * w2;
    }
    #pragma unroll
    for (int k = 0; k < 9; k++)
        g_CU[m][k][t] = a[k];
}

// ---------------- K5: up contraction + post-MLP (double-buffered, n-paired) ----------------
__global__ void __launch_bounds__(512) k_up(const float* __restrict__ Wpost,
                                            const float* __restrict__ bpost,
                                            float* __restrict__ out) {
    __shared__ float CUsm[2][1152];
    __shared__ float Ssm[2][160];
    __shared__ ull  osm[8][HH];
    int t = threadIdx.x;
    int w = t & 127, q = t >> 7;
    int p0 = blockIdx.x * 8;

    bool doCU = (t < 288);
    bool doS  = (t >= 288 && t < 328);
    int  si   = t - 288;

    float4 rCU, rS;
    if (doCU) rCU = ((const float4*)&g_CU[0][0][0])[t];
    if (doS)  rS  = *(const float4*)(&g_S2[0][p0][0] + 4*si);
    if (doCU) *(((float4*)&CUsm[0][0]) + t) = rCU;
    if (doS)  *(((float4*)&Ssm[0][0]) + si) = rS;
    __syncthreads();

    ull acc0 = 0ull, acc1 = 0ull;
    #pragma unroll 1
    for (int m = 0; m < MM; m++) {
        int buf = m & 1;
        if (m + 1 < MM) {
            if (doCU) rCU = ((const float4*)&g_CU[m+1][0][0])[t];
            if (doS)  rS  = *(const float4*)(&g_S2[m+1][p0][0] + 4*si);
        }
        ull cu[9];
        #pragma unroll
        for (int k = 0; k < 9; k++) { float c = CUsm[buf][k*HH + w]; cu[k] = pack2(c, c); }
        #pragma unroll
        for (int i = 0; i < 2; i++) {
            int rp = q*2 + i;
            const float* sp = &Ssm[buf][rp*20];
            ulonglong2 q01 = *(const ulonglong2*)(sp);
            ulonglong2 q23 = *(const ulonglong2*)(sp + 4);
            ulonglong2 q45 = *(const ulonglong2*)(sp + 8);
            ulonglong2 q67 = *(const ulonglong2*)(sp + 12);
            ull a = i ? acc1 : acc0;
            a = add2(a, cu[0]);
            a = fma2(cu[1], q01.x, a);
            a = fma2(cu[2], q01.y, a);
            a = fma2(cu[3], q23.x, a);
            a = fma2(cu[4], q23.y, a);
            a = fma2(cu[5], q45.x, a);
            a = fma2(cu[6], q45.y, a);
            a = fma2(cu[7], q67.x, a);
            a = fma2(cu[8], q67.y, a);
            if (i) acc1 = a; else acc0 = a;
        }
        if (m + 1 < MM) {
            int nb = buf ^ 1;
            if (doCU) *(((float4*)&CUsm[nb][0]) + t) = rCU;
            if (doS)  *(((float4*)&Ssm[nb][0]) + si) = rS;
        }
        __syncthreads();
    }

    osm[q*2 + 0][w] = acc0;
    osm[q*2 + 1][w] = acc1;
    __syncthreads();

    float bp = bpost[w];
    ull fo0 = pack2(bp, bp), fo1 = pack2(bp, bp);
    #pragma unroll 8
    for (int u = 0; u < HH; u++) {
        float wv = Wpost[u*HH + w];
        ull wv2 = pack2(wv, wv);
        fo0 = fma2(osm[q*2 + 0][u], wv2, fo0);
        fo1 = fma2(osm[q*2 + 1][u], wv2, fo1);
    }
    float2 f0 = unpk2(fo0), f1 = unpk2(fo1);
    int r0 = 2*p0 + 4*q;
    out[(long)(r0+0)*HH + w] = f0.x/(1.f+__expf(-f0.x));
    out[(long)(r0+1)*HH + w] = f0.y/(1.f+__expf(-f0.y));
    out[(long)(r0+2)*HH + w] = f1.x/(1.f+__expf(-f1.x));
    out[(long)(r0+3)*HH + w] = f1.y/(1.f+__expf(-f1.y));
}

// ---------------- launch ----------------
extern "C" void kernel_launch(void* const* d_in, const int* in_sizes, int n_in,
                              void* d_out, int out_size) {
    const float* h     = (const float*)d_in[0];
    const float* gc    = (const float*)d_in[1];
    const float* cc    = (const float*)d_in[2];
    const float* gw    = (const float*)d_in[3];
    const float* Wpre  = (const float*)d_in[4];
    const float* bpre  = (const float*)d_in[5];
    const float* Wdown = (const float*)d_in[6];
    const float* Wup   = (const float*)d_in[7];
    const float* Wpost = (const float*)d_in[8];
    const float* bpost = (const float*)d_in[9];
    float* out = (float*)d_out;

    k_sh  <<<MM, 256>>>(gc, cc);
    k_pre <<<NN/16, 128>>>(h, Wpre, bpre, Wdown, gw);
    k_down<<<dim3(MM/GM, NCHUNK), 128>>>();
    k_cu  <<<MM, 128>>>(Wup);
    k_up  <<<NP/8, 512>>>(Wpost, bpost, out);
}

// round 6
// speedup vs baseline: 1.0246x; 1.0246x over previous
#include <cuda_runtime.h>
#include <math.h>

typedef unsigned long long ull;

#define NN 2048
#define MM 128
#define INF 256
#define HH 128
#define NP (NN/2)
#define NCHUNK 8
#define GM 4
#define PTILE 128

#define MIN_STDD 0.3023568
#define MAX_STDD 2.1920868

// ---------------- scratch ----------------
__device__ float g_S2[MM][NP][20];
__device__ float g_hdp2[3][NP][HH][2];
__device__ float g_coarse[NCHUNK][MM][9][HH];
__device__ float g_cr[MM][9][HH];            // reduced coarse
__device__ float g_CU[MM][9][HH];
__device__ unsigned g_cnt[MM/GM];            // zero-init; tail resets

// ---------------- f32x2 helpers ----------------
__device__ __forceinline__ ull pack2(float lo, float hi){ ull r; asm("mov.b64 %0,{%1,%2};":"=l"(r):"f"(lo),"f"(hi)); return r; }
__device__ __forceinline__ float2 unpk2(ull v){ float2 f; asm("mov.b64 {%0,%1},%2;":"=f"(f.x),"=f"(f.y):"l"(v)); return f; }
__device__ __forceinline__ ull fma2(ull a, ull b, ull c){ ull d; asm("fma.rn.f32x2 %0,%1,%2,%3;":"=l"(d):"l"(a),"l"(b),"l"(c)); return d; }
__device__ __forceinline__ ull mul2(ull a, ull b){ ull d; asm("mul.rn.f32x2 %0,%1,%2;":"=l"(d):"l"(a),"l"(b)); return d; }
__device__ __forceinline__ ull add2(ull a, ull b){ ull d; asm("add.rn.f32x2 %0,%1,%2;":"=l"(d):"l"(a),"l"(b)); return d; }
__device__ __forceinline__ float ex2f(float x){ float e; asm("ex2.approx.f32 %0,%1;":"=f"(e):"f"(x)); return e; }

// ---------------- KA: merged spherical harmonics + pre-MLP ----------------
__global__ void __launch_bounds__(256) kA(const float* __restrict__ gc, const float* __restrict__ cc,
                                          const float* __restrict__ h, const float* __restrict__ Wpre,
                                          const float* __restrict__ bpre, const float* __restrict__ Wdown,
                                          const float* __restrict__ gw) {
    if (blockIdx.x < 128) {
        // ---- spherical harmonics for coarse point m ----
        int m = blockIdx.x;
        float cx = cc[3*m], cy = cc[3*m+1], cz = cc[3*m+2];
        const float is3  = 0.5773502691896258f;
        const float is5  = 0.4472135954999579f;
        const float s3i5 = 0.7745966692414834f;
        for (int p = threadIdx.x; p < NP; p += 256) {
            float k[2][9]; float xx2[2];
            #pragma unroll
            for (int hh = 0; hh < 2; hh++) {
                int n = 2*p + hh;
                float dx = gc[3*n]   - cx;
                float dy = gc[3*n+1] - cy;
                float dz = gc[3*n+2] - cz;
                float x2 = dx*dx + dy*dy + dz*dz + 3e-20f;
                float inv = rsqrtf(x2);
                float x = dx*inv, y = dy*inv, z = dz*inv;
                xx2[hh] = x2;
                k[hh][1] = x*is3;  k[hh][2] = y*is3;  k[hh][3] = z*is3;
                k[hh][4] = s3i5*x*z; k[hh][5] = s3i5*x*y;
                k[hh][6] = (y*y - 0.5f*(x*x + z*z))*is5;
                k[hh][7] = s3i5*y*z; k[hh][8] = 0.5f*s3i5*(z*z - x*x);
            }
            float* q = &g_S2[m][p][0];
            *(float4*)(q+0)  = make_float4(k[0][1],k[1][1],k[0][2],k[1][2]);
            *(float4*)(q+4)  = make_float4(k[0][3],k[1][3],k[0][4],k[1][4]);
            *(float4*)(q+8)  = make_float4(k[0][5],k[1][5],k[0][6],k[1][6]);
            *(float4*)(q+12) = make_float4(k[0][7],k[1][7],k[0][8],k[1][8]);
            *(float4*)(q+16) = make_float4(xx2[0],xx2[1],0.f,0.f);
        }
        return;
    }
    // ---- pre-MLP + 3 down projections, 16 rows per block, 256 threads ----
    __shared__ float hT[INF][18];
    __shared__ float sT[HH][18];
    int b  = blockIdx.x - 128;
    int n0 = b * 16;
    int t  = threadIdx.x;
    int w  = t & 127;
    int h4 = (t >> 7) * 4;      // pair base: 0 or 4

    for (int idx = t; idx < 16*INF; idx += 256) {
        int r = idx >> 8, u = idx & 255;
        hT[u][r] = h[(n0 + r)*INF + u];
    }
    __syncthreads();

    ull acc[4];
    {
        float b0 = bpre[w];
        #pragma unroll
        for (int j = 0; j < 4; j++) acc[j] = pack2(b0, b0);
    }
    #pragma unroll 4
    for (int u = 0; u < INF; u++) {
        float wv = Wpre[u*HH + w];
        ull w2 = pack2(wv, wv);
        #pragma unroll
        for (int j = 0; j < 4; j++)
            acc[j] = fma2(*(const ull*)&hT[u][2*(h4+j)], w2, acc[j]);
    }
    #pragma unroll
    for (int j = 0; j < 4; j++) {
        float2 a = unpk2(acc[j]);
        a.x = a.x/(1.f+__expf(-a.x)); a.y = a.y/(1.f+__expf(-a.y));
        *(ull*)&sT[w][2*(h4+j)] = pack2(a.x, a.y);
    }
    __syncthreads();

    double sd = MIN_STDD + (MAX_STDD-MIN_STDD)*(double)w/127.0;
    double iv = 1.0/(2.0*sd*sd);
    const double pi15 = 5.568327996831708;
    float cw = (float)((2.0/3.0)*pow(iv,2.5)/pi15);

    ull gwc[4];
    #pragma unroll
    for (int j = 0; j < 4; j++)
        gwc[j] = pack2(gw[n0+2*(h4+j)]*cw, gw[n0+2*(h4+j)+1]*cw);

    int pbase = b * 8 + h4;
    for (int l = 0; l < 3; l++) {
        const float* Wd = Wdown + l*HH*HH;
        ull a2[4];
        #pragma unroll
        for (int j = 0; j < 4; j++) a2[j] = 0ull;
        #pragma unroll 4
        for (int u = 0; u < HH; u++) {
            float wv = Wd[u*HH + w];
            ull w2 = pack2(wv, wv);
            #pragma unroll
            for (int j = 0; j < 4; j++)
                a2[j] = fma2(*(const ull*)&sT[u][2*(h4+j)], w2, a2[j]);
        }
        #pragma unroll
        for (int j = 0; j < 4; j++)
            *(ull*)&g_hdp2[l][pbase + j][w][0] = mul2(a2[j], gwc[j]);
    }
}

// ---------------- KB: down accumulation + fused last-block chunk reduce ----------------
__global__ void __launch_bounds__(128) k_down() {
    __shared__ float Ssm[GM][PTILE][20];   // 40 KB
    int t  = threadIdx.x;
    int m0 = blockIdx.x * GM;
    int p0 = blockIdx.y * PTILE;

    double sd = MIN_STDD + (MAX_STDD-MIN_STDD)*(double)t/127.0;
    float niv = (float)(-1.4426950408889634/(2.0*sd*sd));
    ull niv2 = pack2(niv, niv);

    for (int i = t; i < GM*PTILE*5; i += 128) {
        int mi = i/(PTILE*5); int rem = i%(PTILE*5); int p = rem/5; int j = rem%5;
        *(float4*)&Ssm[mi][p][4*j] = *(const float4*)&g_S2[m0+mi][p0+p][4*j];
    }
    ull acc[GM][9];
    #pragma unroll
    for (int mi = 0; mi < GM; mi++)
        #pragma unroll
        for (int k = 0; k < 9; k++) acc[mi][k] = 0ull;
    __syncthreads();

    ull h0 = *(const ull*)&g_hdp2[0][p0][t][0];
    ull h1 = *(const ull*)&g_hdp2[1][p0][t][0];
    ull h2 = *(const ull*)&g_hdp2[2][p0][t][0];

    #pragma unroll 1
    for (int p = 0; p < PTILE; p++) {
        ull c0 = h0, c1 = h1, c2 = h2;
        if (p + 1 < PTILE) {
            h0 = *(const ull*)&g_hdp2[0][p0+p+1][t][0];
            h1 = *(const ull*)&g_hdp2[1][p0+p+1][t][0];
            h2 = *(const ull*)&g_hdp2[2][p0+p+1][t][0];
        }
        #pragma unroll
        for (int mi = 0; mi < GM; mi++) {
            const float* sp = &Ssm[mi][p][0];
            ulonglong2 q01 = *(const ulonglong2*)(sp);
            ulonglong2 q23 = *(const ulonglong2*)(sp + 4);
            ulonglong2 q45 = *(const ulonglong2*)(sp + 8);
            ulonglong2 q67 = *(const ulonglong2*)(sp + 12);
            ull x2p = *(const ull*)(sp + 16);
            ull qq  = mul2(x2p, niv2);
            float2 ef = unpk2(qq);
            ull ep  = pack2(ex2f(ef.x), ex2f(ef.y));
            ull rp  = mul2(ep, x2p);
            ull t0 = mul2(c0, rp), t1 = mul2(c1, rp), t2 = mul2(c2, rp);
            acc[mi][0] = add2(acc[mi][0], t0);
            acc[mi][1] = fma2(t1, q01.x, acc[mi][1]);
            acc[mi][2] = fma2(t1, q01.y, acc[mi][2]);
            acc[mi][3] = fma2(t1, q23.x, acc[mi][3]);
            acc[mi][4] = fma2(t2, q23.y, acc[mi][4]);
            acc[mi][5] = fma2(t2, q45.x, acc[mi][5]);
            acc[mi][6] = fma2(t2, q45.y, acc[mi][6]);
            acc[mi][7] = fma2(t2, q67.x, acc[mi][7]);
            acc[mi][8] = fma2(t2, q67.y, acc[mi][8]);
        }
    }
    #pragma unroll
    for (int mi = 0; mi < GM; mi++)
        #pragma unroll
        for (int k = 0; k < 9; k++) {
            float2 f = unpk2(acc[mi][k]);
            g_coarse[blockIdx.y][m0+mi][k][t] = f.x + f.y;
        }

    // ---- last-block-per-m-group chunk reduce (deterministic ch order) ----
    __threadfence();
    __shared__ int lastflag;
    if (t == 0) {
        unsigned old = atomicAdd(&g_cnt[blockIdx.x], 1u);
        lastflag = (old == NCHUNK - 1);
    }
    __syncthreads();
    if (!lastflag) return;
    __threadfence();

    #pragma unroll 1
    for (int mi = 0; mi < GM; mi++) {
        #pragma unroll
        for (int k = 0; k < 9; k++) {
            float s = 0.f;
            #pragma unroll
            for (int ch = 0; ch < NCHUNK; ch++)
                s += g_coarse[ch][m0+mi][k][t];
            g_cr[m0+mi][k][t] = s;
        }
    }
    if (t == 0) g_cnt[blockIdx.x] = 0;   // reset for next replay
}

// ---------------- KC: CU = coarse @ Wup, one block per (m, l) ----------------
__global__ void __launch_bounds__(128) k_gemm(const float* __restrict__ Wup) {
    __shared__ float csm[5][HH];
    int m = blockIdx.x;
    int l = blockIdx.y;
    int t = threadIdx.x;
    const float* Wl = Wup + l*HH*HH;

    if (l == 0) {
        csm[0][t] = g_cr[m][0][t];
        __syncthreads();
        float a = 0.f;
        #pragma unroll 8
        for (int u = 0; u < HH; u++) a += csm[0][u] * Wl[u*HH + t];
        g_CU[m][0][t] = a;
    } else if (l == 1) {
        #pragma unroll
        for (int k = 0; k < 3; k++) csm[k][t] = g_cr[m][1+k][t];
        __syncthreads();
        float a0 = 0.f, a1 = 0.f, a2 = 0.f;
        #pragma unroll 8
        for (int u = 0; u < HH; u++) {
            float wv = Wl[u*HH + t];
            a0 += csm[0][u]*wv; a1 += csm[1][u]*wv; a2 += csm[2][u]*wv;
        }
        g_CU[m][1][t] = a0; g_CU[m][2][t] = a1; g_CU[m][3][t] = a2;
    } else {
        #pragma unroll
        for (int k = 0; k < 5; k++) csm[k][t] = g_cr[m][4+k][t];
        __syncthreads();
        float a0=0.f,a1=0.f,a2=0.f,a3=0.f,a4=0.f;
        #pragma unroll 8
        for (int u = 0; u < HH; u++) {
            float wv = Wl[u*HH + t];
            a0 += csm[0][u]*wv; a1 += csm[1][u]*wv; a2 += csm[2][u]*wv;
            a3 += csm[3][u]*wv; a4 += csm[4][u]*wv;
        }
        g_CU[m][4][t]=a0; g_CU[m][5][t]=a1; g_CU[m][6][t]=a2;
        g_CU[m][7][t]=a3; g_CU[m][8][t]=a4;
    }
}

// ---------------- KD: up contraction + post-MLP, 4 m per stage ----------------
#define CHM 4
__global__ void __launch_bounds__(512) k_up(const float* __restrict__ Wpost,
                                            const float* __restrict__ bpost,
                                            float* __restrict__ out) {
    __shared__ float CUs[2][CHM*1152];   // 36.8 KB
    __shared__ float Ss[2][CHM*160];     // 5.1 KB
    __shared__ ull  osm[8][HH];          // 8 KB
    int t = threadIdx.x;
    int w = t & 127, q = t >> 7;
    int p0 = blockIdx.x * 8;

    int i0 = t, i1 = t + 512, i2 = t + 1024;
    bool has2 = (i2 < 1312);

    // fetch lambda: flat index i over [CU: 1152 float4][S: 160 float4]
    auto fetch = [&](int s, int i) -> float4 {
        int mb = CHM*s;
        if (i < 1152) {
            int mi = i / 288, j = i % 288;
            return ((const float4*)&g_CU[mb+mi][0][0])[j];
        } else {
            int ii = i - 1152;
            int mi = ii / 40, j = ii % 40;
            return ((const float4*)&g_S2[mb+mi][p0][0])[j];
        }
    };
    auto store = [&](int buf, int i, float4 v) {
        if (i < 1152) ((float4*)&CUs[buf][0])[i] = v;
        else          ((float4*)&Ss[buf][0])[i-1152] = v;
    };

    float4 r0 = fetch(0, i0), r1 = fetch(0, i1), r2;
    if (has2) r2 = fetch(0, i2);
    store(0, i0, r0); store(0, i1, r1); if (has2) store(0, i2, r2);
    __syncthreads();

    ull acc0 = 0ull, acc1 = 0ull;
    #pragma unroll 1
    for (int s = 0; s < MM/CHM; s++) {
        int buf = s & 1;
        if (s + 1 < MM/CHM) {
            r0 = fetch(s+1, i0); r1 = fetch(s+1, i1);
            if (has2) r2 = fetch(s+1, i2);
        }
        #pragma unroll
        for (int mi = 0; mi < CHM; mi++) {
            const float* cub = &CUs[buf][mi*1152];
            ull cu[9];
            #pragma unroll
            for (int k = 0; k < 9; k++) { float c = cub[k*HH + w]; cu[k] = pack2(c, c); }
            #pragma unroll
            for (int i = 0; i < 2; i++) {
                const float* sp = &Ss[buf][mi*160 + (q*2 + i)*20];
                ulonglong2 q01 = *(const ulonglong2*)(sp);
                ulonglong2 q23 = *(const ulonglong2*)(sp + 4);
                ulonglong2 q45 = *(const ulonglong2*)(sp + 8);
                ulonglong2 q67 = *(const ulonglong2*)(sp + 12);
                ull a = i ? acc1 : acc0;
                a = add2(a, cu[0]);
                a = fma2(cu[1], q01.x, a);
                a = fma2(cu[2], q01.y, a);
                a = fma2(cu[3], q23.x, a);
                a = fma2(cu[4], q23.y, a);
                a = fma2(cu[5], q45.x, a);
                a = fma2(cu[6], q45.y, a);
                a = fma2(cu[7], q67.x, a);
                a = fma2(cu[8], q67.y, a);
                if (i) acc1 = a; else acc0 = a;
            }
        }
        if (s + 1 < MM/CHM) {
            int nb = buf ^ 1;
            store(nb, i0, r0); store(nb, i1, r1); if (has2) store(nb, i2, r2);
        }
        __syncthreads();
    }

    osm[q*2 + 0][w] = acc0;
    osm[q*2 + 1][w] = acc1;
    __syncthreads();

    float bp = bpost[w];
    ull fo0 = pack2(bp, bp), fo1 = pack2(bp, bp);
    #pragma unroll 8
    for (int u = 0; u < HH; u++) {
        float wv = Wpost[u*HH + w];
        ull wv2 = pack2(wv, wv);
        fo0 = fma2(osm[q*2 + 0][u], wv2, fo0);
        fo1 = fma2(osm[q*2 + 1][u], wv2, fo1);
    }
    float2 f0 = unpk2(fo0), f1 = unpk2(fo1);
    int r0i = 2*p0 + 4*q;
    out[(long)(r0i+0)*HH + w] = f0.x/(1.f+__expf(-f0.x));
    out[(long)(r0i+1)*HH + w] = f0.y/(1.f+__expf(-f0.y));
    out[(long)(r0i+2)*HH + w] = f1.x/(1.f+__expf(-f1.x));
    out[(long)(r0i+3)*HH + w] = f1.y/(1.f+__expf(-f1.y));
}

// ---------------- launch ----------------
extern "C" void kernel_launch(void* const* d_in, const int* in_sizes, int n_in,
                              void* d_out, int out_size) {
    const float* h     = (const float*)d_in[0];
    const float* gc    = (const float*)d_in[1];
    const float* cc    = (const float*)d_in[2];
    const float* gw    = (const float*)d_in[3];
    const float* Wpre  = (const float*)d_in[4];
    const float* bpre  = (const float*)d_in[5];
    const float* Wdown = (const float*)d_in[6];
    const float* Wup   = (const float*)d_in[7];
    const float* Wpost = (const float*)d_in[8];
    const float* bpost = (const float*)d_in[9];
    float* out = (float*)d_out;

    kA    <<<256, 256>>>(gc, cc, h, Wpre, bpre, Wdown, gw);
    k_down<<<dim3(MM/GM, NCHUNK), 128>>>();
    k_gemm<<<dim3(MM, 3), 128>>>(Wup);
    k_up  <<<NP/8, 512>>>(Wpost, bpost, out);
}